// round 2
// baseline (speedup 1.0000x reference)
#include <cuda_runtime.h>

#define NSETS 8
#define NPTS  4096
#define DF    16
#define KK    16
#define TPB   256
#define TILE  256

__global__ __launch_bounds__(TPB)
void knn_graph_kernel(const float* __restrict__ x, float* __restrict__ out,
                      long long out_elems) {
    __shared__ float sc[TILE * DF];   // candidate tile, row-major [TILE][DF]
    __shared__ float sc2[TILE];       // squared norms of candidates

    const int tid = threadIdx.x;
    const int b   = blockIdx.x;
    const int set = b / (NPTS / TPB);
    const int row = (b % (NPTS / TPB)) * TPB + tid;
    const float* __restrict__ xs = x + (size_t)set * NPTS * DF;

    // load query row into registers
    float q[DF];
#pragma unroll
    for (int d = 0; d < DF; ++d) q[d] = xs[row * DF + d];

    // ||q||^2 with same sequential order as reference sum
    float q2 = 0.f;
#pragma unroll
    for (int d = 0; d < DF; ++d) q2 += q[d] * q[d];

    // top-K (ascending) in registers
    float bd[KK];
    int   bi[KK];
#pragma unroll
    for (int p = 0; p < KK; ++p) { bd[p] = 3.4028235e38f; bi[p] = 0; }

    for (int j0 = 0; j0 < NPTS; j0 += TILE) {
        __syncthreads();   // protect smem reuse across tiles
        // cooperative, fully coalesced tile load: TILE*DF floats
#pragma unroll
        for (int t = 0; t < (TILE * DF) / TPB; ++t) {
            int idx = t * TPB + tid;
            sc[idx] = xs[j0 * DF + idx];
        }
        __syncthreads();
        // each thread computes the squared norm of its own candidate row
        {
            float s = 0.f;
#pragma unroll
            for (int d = 0; d < DF; ++d) {
                float v = sc[tid * DF + d];
                s += v * v;
            }
            sc2[tid] = s;
        }
        __syncthreads();

#pragma unroll 2
        for (int j = 0; j < TILE; ++j) {
            float acc = 0.f;
#pragma unroll
            for (int d = 0; d < DF; ++d) acc += q[d] * sc[j * DF + d];
            float dist = q2 + sc2[j] - 2.0f * acc;

            // strict '<' keeps lowest-index-first on ties (matches lax.top_k)
            if (dist < bd[KK - 1]) {
                int idx = j0 + j;
#pragma unroll
                for (int p = KK - 1; p > 0; --p) {
                    bool shift = (bd[p - 1] > dist);
                    if (bd[p] > dist) {
                        bd[p] = shift ? bd[p - 1] : dist;
                        bi[p] = shift ? bi[p - 1] : idx;
                    }
                }
                if (bd[0] > dist) { bd[0] = dist; bi[0] = idx; }
            }
        }
    }

    // write outputs: concat(src, dst, topk_dist) flattened as float32
    const long long E    = (long long)NSETS * NPTS * KK;
    const long long base = ((long long)set * NPTS + row) * KK;
    const float srcv = (float)(set * NPTS + row);
    const int   off  = set * NPTS;

    if (out_elems >= 3 * E) {
#pragma unroll
        for (int p = 0; p < KK; ++p) {
            out[base + p]         = srcv;
            out[E + base + p]     = (float)(off + bi[p]);
            out[2 * E + base + p] = bd[p];
        }
    } else {
        // fallback: dist-only output
#pragma unroll
        for (int p = 0; p < KK; ++p) out[base + p] = bd[p];
    }
}

extern "C" void kernel_launch(void* const* d_in, const int* in_sizes, int n_in,
                              void* d_out, int out_size) {
    const float* x = (const float*)d_in[0];
    float* out = (float*)d_out;
    dim3 grid((NSETS * NPTS) / TPB);
    knn_graph_kernel<<<grid, TPB>>>(x, out, (long long)out_size);
}

// round 4
// speedup vs baseline: 1.3352x; 1.3352x over previous
#include <cuda_runtime.h>
#include <cfloat>

#define NSETS  8
#define NPTS   4096
#define DF     16
#define KK     16
#define TPB    256
#define TILE   256
#define SPLITS 4
#define CSPLIT (NPTS / SPLITS)   // 1024 candidates per split
#define QT     (NPTS / TPB)      // 16 query tiles per set

// scratch for partial top-k per (query, split)
__device__ float g_pd[(size_t)NSETS * NPTS * SPLITS * KK];
__device__ int   g_pi[(size_t)NSETS * NPTS * SPLITS * KK];

__device__ __forceinline__ unsigned long long pack2(float lo, float hi) {
    unsigned long long r;
    asm("mov.b64 %0, {%1, %2};" : "=l"(r) : "f"(lo), "f"(hi));
    return r;
}
__device__ __forceinline__ void unpack2(unsigned long long v, float& lo, float& hi) {
    asm("mov.b64 {%0, %1}, %2;" : "=f"(lo), "=f"(hi) : "l"(v));
}
__device__ __forceinline__ unsigned long long mul2(unsigned long long a, unsigned long long b) {
    unsigned long long d;
    asm("mul.rn.f32x2 %0, %1, %2;" : "=l"(d) : "l"(a), "l"(b));
    return d;
}
__device__ __forceinline__ void fma2(unsigned long long& d, unsigned long long a, unsigned long long b) {
    asm("fma.rn.f32x2 %0, %1, %2, %0;" : "+l"(d) : "l"(a), "l"(b));
}
__device__ __forceinline__ unsigned long long add2(unsigned long long a, unsigned long long b) {
    unsigned long long d;
    asm("add.rn.f32x2 %0, %1, %2;" : "=l"(d) : "l"(a), "l"(b));
    return d;
}

__global__ __launch_bounds__(TPB, 4)
void knn_partial(const float* __restrict__ x) {
    __shared__ float sc[TILE * DF];   // candidate tile rows (row-major)
    __shared__ float sc2[TILE];       // candidate squared norms

    const int tid = threadIdx.x;
    const int b   = blockIdx.x;
    const int s   = b % SPLITS;
    const int qt  = (b / SPLITS) % QT;
    const int set = b / (SPLITS * QT);
    const int row = qt * TPB + tid;
    const float* __restrict__ xs = x + (size_t)set * NPTS * DF;

    // query row, packed into 8 f32x2 lanes
    const float4* qp = reinterpret_cast<const float4*>(xs + (size_t)row * DF);
    float4 q0 = qp[0], q1 = qp[1], q2v = qp[2], q3 = qp[3];
    unsigned long long qq[8];
    qq[0] = pack2(q0.x, q0.y); qq[1] = pack2(q0.z, q0.w);
    qq[2] = pack2(q1.x, q1.y); qq[3] = pack2(q1.z, q1.w);
    qq[4] = pack2(q2v.x, q2v.y); qq[5] = pack2(q2v.z, q2v.w);
    qq[6] = pack2(q3.x, q3.y); qq[7] = pack2(q3.z, q3.w);
    float qn = q0.x*q0.x + q0.y*q0.y + q0.z*q0.z + q0.w*q0.w
             + q1.x*q1.x + q1.y*q1.y + q1.z*q1.z + q1.w*q1.w
             + q2v.x*q2v.x + q2v.y*q2v.y + q2v.z*q2v.z + q2v.w*q2v.w
             + q3.x*q3.x + q3.y*q3.y + q3.z*q3.z + q3.w*q3.w;

    float bd[KK];
    int   bi[KK];
#pragma unroll
    for (int p = 0; p < KK; ++p) { bd[p] = FLT_MAX; bi[p] = 0; }

    const int jbeg = s * CSPLIT;
    for (int j0 = jbeg; j0 < jbeg + CSPLIT; j0 += TILE) {
        __syncthreads();
        // thread tid stages candidate row (j0+tid) and its norm
        {
            const float4* src = reinterpret_cast<const float4*>(xs + (size_t)(j0 + tid) * DF);
            float4 c0 = src[0], c1 = src[1], c2 = src[2], c3 = src[3];
            float4* dst = reinterpret_cast<float4*>(sc + tid * DF);
            dst[0] = c0; dst[1] = c1; dst[2] = c2; dst[3] = c3;
            sc2[tid] = c0.x*c0.x + c0.y*c0.y + c0.z*c0.z + c0.w*c0.w
                     + c1.x*c1.x + c1.y*c1.y + c1.z*c1.z + c1.w*c1.w
                     + c2.x*c2.x + c2.y*c2.y + c2.z*c2.z + c2.w*c2.w
                     + c3.x*c3.x + c3.y*c3.y + c3.z*c3.z + c3.w*c3.w;
        }
        __syncthreads();

        for (int j = 0; j < TILE; ++j) {
            const ulonglong2* cp = reinterpret_cast<const ulonglong2*>(sc + j * DF);
            ulonglong2 v0 = cp[0], v1 = cp[1], v2 = cp[2], v3 = cp[3];
            unsigned long long a0 = mul2(qq[0], v0.x);
            unsigned long long a1 = mul2(qq[1], v0.y);
            fma2(a0, qq[2], v1.x);
            fma2(a1, qq[3], v1.y);
            fma2(a0, qq[4], v2.x);
            fma2(a1, qq[5], v2.y);
            fma2(a0, qq[6], v3.x);
            fma2(a1, qq[7], v3.y);
            unsigned long long acc = add2(a0, a1);
            float dlo, dhi;
            unpack2(acc, dlo, dhi);
            float dot  = dlo + dhi;
            float dist = fmaf(-2.0f, dot, qn + sc2[j]);

            if (dist < bd[KK - 1]) {
                int idx = j0 + j;
#pragma unroll
                for (int p = KK - 1; p > 0; --p) {
                    bool shift = (bd[p - 1] > dist);
                    if (bd[p] > dist) {
                        bd[p] = shift ? bd[p - 1] : dist;
                        bi[p] = shift ? bi[p - 1] : idx;
                    }
                }
                if (bd[0] > dist) { bd[0] = dist; bi[0] = idx; }
            }
        }
    }

    const size_t base = ((size_t)(set * NPTS + row) * SPLITS + s) * KK;
#pragma unroll
    for (int p = 0; p < KK; ++p) {
        g_pd[base + p] = bd[p];
        g_pi[base + p] = bi[p];
    }
}

__global__ __launch_bounds__(TPB)
void knn_merge(float* __restrict__ out, long long out_elems) {
    const int q = blockIdx.x * blockDim.x + threadIdx.x;  // global query id
    if (q >= NSETS * NPTS) return;
    const int set = q / NPTS;
    const int row = q % NPTS;

    float bd[KK];
    int   bi[KK];
#pragma unroll
    for (int p = 0; p < KK; ++p) { bd[p] = FLT_MAX; bi[p] = 0; }

    const size_t qbase = (size_t)q * SPLITS * KK;
#pragma unroll
    for (int s = 0; s < SPLITS; ++s) {
        const size_t sb = qbase + (size_t)s * KK;
        for (int p = 0; p < KK; ++p) {
            float dist = g_pd[sb + p];
            if (dist >= bd[KK - 1]) break;  // split list sorted ascending
            int idx = g_pi[sb + p];
#pragma unroll
            for (int t = KK - 1; t > 0; --t) {
                bool shift = (bd[t - 1] > dist);
                if (bd[t] > dist) {
                    bd[t] = shift ? bd[t - 1] : dist;
                    bi[t] = shift ? bi[t - 1] : idx;
                }
            }
            if (bd[0] > dist) { bd[0] = dist; bi[0] = idx; }
        }
    }

    const long long E    = (long long)NSETS * NPTS * KK;
    const long long base = (long long)q * KK;
    const float srcv = (float)(set * NPTS + row);
    const int   off  = set * NPTS;

    if (out_elems >= 3 * E) {
#pragma unroll
        for (int p = 0; p < KK; ++p) {
            out[base + p]         = srcv;
            out[E + base + p]     = (float)(off + bi[p]);
            out[2 * E + base + p] = bd[p];
        }
    } else {
#pragma unroll
        for (int p = 0; p < KK; ++p) out[base + p] = bd[p];
    }
}

extern "C" void kernel_launch(void* const* d_in, const int* in_sizes, int n_in,
                              void* d_out, int out_size) {
    const float* x = (const float*)d_in[0];
    float* out = (float*)d_out;
    knn_partial<<<NSETS * QT * SPLITS, TPB>>>(x);
    knn_merge<<<(NSETS * NPTS + TPB - 1) / TPB, TPB>>>(out, (long long)out_size);
}

// round 5
// speedup vs baseline: 1.4962x; 1.1206x over previous
#include <cuda_runtime.h>
#include <cfloat>

#define NSETS  8
#define NPTS   4096
#define DF     16
#define KK     16
#define TPB    128
#define TILE   256
#define SPLITS 2
#define CSPLIT (NPTS / SPLITS)   // 2048 candidates per split
#define QT     (NPTS / TPB)      // 32 query tiles per set

// scratch for partial top-k per (query, split)
__device__ float g_pd[(size_t)NSETS * NPTS * SPLITS * KK];
__device__ int   g_pi[(size_t)NSETS * NPTS * SPLITS * KK];

__device__ __forceinline__ unsigned long long pack2(float lo, float hi) {
    unsigned long long r;
    asm("mov.b64 %0, {%1, %2};" : "=l"(r) : "f"(lo), "f"(hi));
    return r;
}
__device__ __forceinline__ void unpack2(unsigned long long v, float& lo, float& hi) {
    asm("mov.b64 {%0, %1}, %2;" : "=f"(lo), "=f"(hi) : "l"(v));
}
__device__ __forceinline__ void fma2(unsigned long long& d, unsigned long long a, unsigned long long b) {
    asm("fma.rn.f32x2 %0, %1, %2, %0;" : "+l"(d) : "l"(a), "l"(b));
}
__device__ __forceinline__ unsigned long long mul2(unsigned long long a, unsigned long long b) {
    unsigned long long d;
    asm("mul.rn.f32x2 %0, %1, %2;" : "=l"(d) : "l"(a), "l"(b));
    return d;
}
__device__ __forceinline__ unsigned long long add2(unsigned long long a, unsigned long long b) {
    unsigned long long d;
    asm("add.rn.f32x2 %0, %1, %2;" : "=l"(d) : "l"(a), "l"(b));
    return d;
}

template<int K>
__device__ __forceinline__ void insert_sorted(float (&bd)[K], int (&bi)[K],
                                              float dist, int idx) {
#pragma unroll
    for (int p = K - 1; p > 0; --p) {
        bool shift = (bd[p - 1] > dist);
        if (bd[p] > dist) {
            bd[p] = shift ? bd[p - 1] : dist;
            bi[p] = shift ? bi[p - 1] : idx;
        }
    }
    if (bd[0] > dist) { bd[0] = dist; bi[0] = idx; }
}

__global__ __launch_bounds__(TPB, 4)
void knn_partial(const float* __restrict__ x) {
    __shared__ float sc[TILE * DF];   // candidate tile rows (row-major)
    __shared__ float sch[TILE];       // -0.5 * squared norm of candidates

    const int tid = threadIdx.x;
    const int b   = blockIdx.x;
    const int s   = b % SPLITS;
    const int qt  = (b / SPLITS) % QT;
    const int set = b / (SPLITS * QT);
    const int row = qt * TPB + tid;
    const float* __restrict__ xs = x + (size_t)set * NPTS * DF;

    // query row, packed into 8 f32x2 lanes
    const float4* qp = reinterpret_cast<const float4*>(xs + (size_t)row * DF);
    float4 q0 = qp[0], q1 = qp[1], q2v = qp[2], q3 = qp[3];
    unsigned long long qq[8];
    qq[0] = pack2(q0.x, q0.y);   qq[1] = pack2(q0.z, q0.w);
    qq[2] = pack2(q1.x, q1.y);   qq[3] = pack2(q1.z, q1.w);
    qq[4] = pack2(q2v.x, q2v.y); qq[5] = pack2(q2v.z, q2v.w);
    qq[6] = pack2(q3.x, q3.y);   qq[7] = pack2(q3.z, q3.w);
    float qn = q0.x*q0.x + q0.y*q0.y + q0.z*q0.z + q0.w*q0.w
             + q1.x*q1.x + q1.y*q1.y + q1.z*q1.z + q1.w*q1.w
             + q2v.x*q2v.x + q2v.y*q2v.y + q2v.z*q2v.z + q2v.w*q2v.w
             + q3.x*q3.x + q3.y*q3.y + q3.z*q3.z + q3.w*q3.w;
    const float qh = -0.5f * qn;

    float bd[KK];
    int   bi[KK];
#pragma unroll
    for (int p = 0; p < KK; ++p) { bd[p] = FLT_MAX; bi[p] = 0; }

    const int jbeg = s * CSPLIT;
    for (int j0 = jbeg; j0 < jbeg + CSPLIT; j0 += TILE) {
        __syncthreads();
        // each thread stages 2 candidate rows (TILE=256, TPB=128)
#pragma unroll
        for (int t = 0; t < TILE / TPB; ++t) {
            const int r = t * TPB + tid;
            const float4* src = reinterpret_cast<const float4*>(xs + (size_t)(j0 + r) * DF);
            float4 c0 = src[0], c1 = src[1], c2 = src[2], c3 = src[3];
            float4* dst = reinterpret_cast<float4*>(sc + r * DF);
            dst[0] = c0; dst[1] = c1; dst[2] = c2; dst[3] = c3;
            float n = c0.x*c0.x + c0.y*c0.y + c0.z*c0.z + c0.w*c0.w
                    + c1.x*c1.x + c1.y*c1.y + c1.z*c1.z + c1.w*c1.w
                    + c2.x*c2.x + c2.y*c2.y + c2.z*c2.z + c2.w*c2.w
                    + c3.x*c3.x + c3.y*c3.y + c3.z*c3.z + c3.w*c3.w;
            sch[r] = -0.5f * n;
        }
        __syncthreads();

        // 2 candidates per iteration, independent FMA chains for ILP
        for (int j = 0; j < TILE; j += 2) {
            const ulonglong2* cpa = reinterpret_cast<const ulonglong2*>(sc + j * DF);
            const ulonglong2* cpb = reinterpret_cast<const ulonglong2*>(sc + (j + 1) * DF);
            ulonglong2 a0v = cpa[0], a1v = cpa[1], a2v = cpa[2], a3v = cpa[3];
            ulonglong2 b0v = cpb[0], b1v = cpb[1], b2v = cpb[2], b3v = cpb[3];

            // acc starts at (qh, ch_j) so final sum = dot - 0.5(qn + c2)
            unsigned long long aA = pack2(qh, sch[j]);
            unsigned long long aB = mul2(qq[1], a0v.y);
            unsigned long long bA = pack2(qh, sch[j + 1]);
            unsigned long long bB = mul2(qq[1], b0v.y);
            fma2(aA, qq[0], a0v.x);  fma2(bA, qq[0], b0v.x);
            fma2(aB, qq[3], a1v.y);  fma2(bB, qq[3], b1v.y);
            fma2(aA, qq[2], a1v.x);  fma2(bA, qq[2], b1v.x);
            fma2(aB, qq[5], a2v.y);  fma2(bB, qq[5], b2v.y);
            fma2(aA, qq[4], a2v.x);  fma2(bA, qq[4], b2v.x);
            fma2(aB, qq[7], a3v.y);  fma2(bB, qq[7], b3v.y);
            fma2(aA, qq[6], a3v.x);  fma2(bA, qq[6], b3v.x);

            unsigned long long sA = add2(aA, aB);
            unsigned long long sB = add2(bA, bB);
            float alo, ahi, blo, bhi;
            unpack2(sA, alo, ahi);
            unpack2(sB, blo, bhi);
            float d0 = -2.0f * (alo + ahi);   // = qn + c2 - 2*dot
            float d1 = -2.0f * (blo + bhi);

            const float thr = bd[KK - 1];
            if (d0 < thr || d1 < thr) {
                if (d0 < bd[KK - 1]) insert_sorted(bd, bi, d0, j0 + j);
                if (d1 < bd[KK - 1]) insert_sorted(bd, bi, d1, j0 + j + 1);
            }
        }
    }

    const size_t base = ((size_t)(set * NPTS + row) * SPLITS + s) * KK;
#pragma unroll
    for (int p = 0; p < KK; ++p) {
        g_pd[base + p] = bd[p];
        g_pi[base + p] = bi[p];
    }
}

__global__ __launch_bounds__(TPB)
void knn_merge(float* __restrict__ out, long long out_elems) {
    const int q = blockIdx.x * blockDim.x + threadIdx.x;  // global query id
    if (q >= NSETS * NPTS) return;
    const int set = q / NPTS;
    const int row = q % NPTS;

    float bd[KK];
    int   bi[KK];
#pragma unroll
    for (int p = 0; p < KK; ++p) { bd[p] = FLT_MAX; bi[p] = 0; }

    const size_t qbase = (size_t)q * SPLITS * KK;
#pragma unroll
    for (int s = 0; s < SPLITS; ++s) {
        const size_t sb = qbase + (size_t)s * KK;
        // vectorized read of the sorted split list
        float4 dv[KK / 4];
        int4   iv[KK / 4];
#pragma unroll
        for (int t = 0; t < KK / 4; ++t) {
            dv[t] = reinterpret_cast<const float4*>(g_pd + sb)[t];
            iv[t] = reinterpret_cast<const int4*>(g_pi + sb)[t];
        }
        const float* dvf = reinterpret_cast<const float*>(dv);
        const int*   ivf = reinterpret_cast<const int*>(iv);
        for (int p = 0; p < KK; ++p) {
            float dist = dvf[p];
            if (dist >= bd[KK - 1]) break;  // split list sorted ascending
            insert_sorted(bd, bi, dist, ivf[p]);
        }
    }

    const long long E    = (long long)NSETS * NPTS * KK;
    const long long base = (long long)q * KK;
    const float srcv = (float)(set * NPTS + row);
    const int   off  = set * NPTS;

    if (out_elems >= 3 * E) {
#pragma unroll
        for (int p = 0; p < KK; ++p) {
            out[base + p]         = srcv;
            out[E + base + p]     = (float)(off + bi[p]);
            out[2 * E + base + p] = bd[p];
        }
    } else {
#pragma unroll
        for (int p = 0; p < KK; ++p) out[base + p] = bd[p];
    }
}

extern "C" void kernel_launch(void* const* d_in, const int* in_sizes, int n_in,
                              void* d_out, int out_size) {
    const float* x = (const float*)d_in[0];
    float* out = (float*)d_out;
    knn_partial<<<NSETS * QT * SPLITS, TPB>>>(x);
    knn_merge<<<(NSETS * NPTS + TPB - 1) / TPB, TPB>>>(out, (long long)out_size);
}